// round 17
// baseline (speedup 1.0000x reference)
#include <cuda_runtime.h>
#include <cstdint>

#define BATCH 4
#define NPTS  8192
#define NTOT  (BATCH * NPTS)     // 32768
#define HH    2048
#define WW    2048
#define KOUT  1024
#define RAD   4
#define NBUCK 4096
#define CGRID 128                // 2048 / 16
#define NCELL (CGRID * CGRID)    // 16384 cells per batch
#define CCAP  16                 // slots per cell (lambda=0.5 -> overflow ~0)

typedef unsigned long long ull;

// Persistent scratch. g_cellcnt restored to zero in P3 every launch;
// g_cells needs no cleanup (counts gate validity); g_hist zeroed in P1.
__device__ __align__(16) unsigned g_cellcnt[BATCH * NCELL];        // 256 KB
__device__ __align__(16) ull      g_cells[BATCH * NCELL * CCAP];   // 8 MB
__device__ __align__(16) ull      g_keys[NTOT];
__device__ __align__(16) unsigned g_hist[BATCH * NBUCK];

__device__ unsigned g_bar_count[BATCH];
__device__ volatile unsigned g_bar_gen[BATCH];

// 8-block per-batch barrier (blocks 8b .. 8b+7). Generation-based -> reusable.
__device__ __forceinline__ void batch_bar(int c) {
    __syncthreads();
    if (threadIdx.x == 0) {
        __threadfence();
        unsigned gen = g_bar_gen[c];
        if (atomicAdd(&g_bar_count[c], 1u) == 7u) {
            g_bar_count[c] = 0;
            __threadfence();
            g_bar_gen[c] = gen + 1;
        } else {
            while (g_bar_gen[c] == gen) { }
        }
        __threadfence();
    }
    __syncthreads();
}

__device__ __forceinline__ unsigned bucket_of(ull k) {
    unsigned m = (unsigned)(k >> 32);
    if (m & 0x80000000u) {        // survivor (score >= 0)
        float sc = __uint_as_float(m & 0x7FFFFFFFu);
        int bu = (int)(sc * (float)NBUCK);
        return (unsigned)min(max(bu, 0), NBUCK - 1);
    }
    return 0u;                    // culled (-inf)
}

// ---------------------------------------------------------------------------
// ONE kernel: 32 blocks x 1024 threads, 1 thread = 1 keypoint.
// Blocks 8b..8b+7 own batch b. P1 insert -> bar -> P2 cell NMS + key/hist ->
// bar -> P3 zero own cell -> block 8b: histogram top-k select (1024-thread
// shape) + outputs. Others exit.
// ---------------------------------------------------------------------------
__global__ void __launch_bounds__(1024) fused_kernel(const float* __restrict__ lafs,
                                                     const float* __restrict__ scores,
                                                     float* __restrict__ out) {
    __shared__ ull      cand[2048];           // 16 KB candidate keys
    __shared__ unsigned cur[NBUCK];           // 16 KB scatter cursors
    __shared__ unsigned aux[40];              // warp sums + bstar

    int t = threadIdx.x;
    int b = blockIdx.x;
    int i = b * 1024 + t;                     // keypoint id
    int batch = b >> 3;
    int li = i & (NPTS - 1);

    // ---- P1: hist zero (first 4096 threads of each batch) + cell insert ----
    if (li < NBUCK) g_hist[batch * NBUCK + li] = 0u;

    const float2* lp = reinterpret_cast<const float2*>(lafs);
    float x = lp[3 * i + 1].x;   // laf[:,0,2]
    float y = lp[3 * i + 2].y;   // laf[:,1,2]
    int xi = (int)rintf(x); xi = min(max(xi, 0), WW - 1);  // rintf == jnp.round (RNE)
    int yi = (int)rintf(y); yi = min(max(yi, 0), HH - 1);
    float s = scores[i];
    unsigned sbits = __float_as_uint(s);

    unsigned cell = ((unsigned)batch << 14) | ((unsigned)(yi >> 4) << 7) | (unsigned)(xi >> 4);
    unsigned slot = atomicAdd(&g_cellcnt[cell], 1u);
    if (slot < CCAP)
        g_cells[((size_t)cell << 4) + slot] =
            ((ull)sbits << 32) | ((unsigned)yi << 11) | (unsigned)xi;

    batch_bar(batch);            // all inserts + hist zeroes of this batch done

    // ---- P2: NMS by keypoint comparison over <=4 cells.
    // survive_i <=> no keypoint within Chebyshev distance 4 has higher score
    // (exactly the reference's scatter-max + reduce_window test). ----
    int y0 = max(yi - RAD, 0), y1 = min(yi + RAD, HH - 1);
    int x0 = max(xi - RAD, 0), x1 = min(xi + RAD, WW - 1);
    int cy0 = y0 >> 4, cy1 = y1 >> 4;
    int cx0 = x0 >> 4, cx1 = x1 >> 4;

    bool culled = false;
    #pragma unroll
    for (int u = 0; u < 4; ++u) {
        int cy = (u & 2) ? cy1 : cy0;
        int cx = (u & 1) ? cx1 : cx0;
        unsigned c = ((unsigned)batch << 14) | ((unsigned)cy << 7) | (unsigned)cx;
        unsigned cnt = min(g_cellcnt[c], (unsigned)CCAP);
        const ull* cp = g_cells + ((size_t)c << 4);
        for (unsigned k2 = 0; k2 < cnt; ++k2) {
            ull rec = __ldg(cp + k2);
            int rx = (int)(rec & 2047u);
            int ry = (int)((rec >> 11) & 2047u);
            if (rx >= x0 && rx <= x1 && ry >= y0 && ry <= y1) {
                unsigned rs = (unsigned)(rec >> 32);      // positive floats: uint order
                if (rs > sbits) culled = true;
            }
        }
    }

    unsigned sb = culled ? 0xFF800000u : sbits;           // -inf if culled
    unsigned m  = (sb & 0x80000000u) ? ~sb : (sb | 0x80000000u);
    ull key = ((ull)m << 32) | (unsigned)(~i);
    g_keys[i] = key;
    atomicAdd(&g_hist[batch * NBUCK + bucket_of(key)], 1u);   // REDG, spread wide

    batch_bar(batch);            // NMS reads + key stores + hist adds done

    // ---- P3: zero own cell (duplicates benign) ----
    g_cellcnt[cell] = 0u;

    // ---- select: one 1024-thread block per batch ----
    if (b & 7) return;

    int base = batch << 13;

    // load finished histogram (uint4 per thread) + keys (4 x LDG.128)
    uint4 hv = reinterpret_cast<const uint4*>(g_hist + batch * NBUCK)[t];
    ull k8[8];
    {
        const ulonglong2* kv = reinterpret_cast<const ulonglong2*>(g_keys + base);
        #pragma unroll
        for (int r = 0; r < 4; ++r) {
            ulonglong2 v2 = kv[(r << 10) + t];
            k8[2 * r] = v2.x;
            k8[2 * r + 1] = v2.y;
        }
    }
    if (t == 0) aux[34] = 0;                  // bstar
    __syncthreads();

    // block suffix scan: thread t owns buckets 4t..4t+3
    unsigned h0 = hv.x, h1 = hv.y, h2 = hv.z, h3 = hv.w;
    unsigned s4 = h0 + h1 + h2 + h3;
    unsigned lane = t & 31, wid = t >> 5;
    unsigned pref = s4;
    #pragma unroll
    for (int d = 1; d < 32; d <<= 1) {
        unsigned vv = __shfl_up_sync(0xffffffffu, pref, d);
        if (lane >= d) pref += vv;
    }
    if (lane == 31) aux[2 + wid] = pref;      // warp totals
    __syncthreads();
    if (wid == 0) {
        unsigned wv = aux[2 + lane];
        #pragma unroll
        for (int d = 1; d < 32; d <<= 1) {
            unsigned vv = __shfl_up_sync(0xffffffffu, wv, d);
            if (lane >= d) wv += vv;
        }
        aux[2 + lane] = wv;                   // inclusive warp-total scan
    }
    __syncthreads();
    unsigned warpoff = (wid > 0) ? aux[2 + wid - 1] : 0;
    unsigned incl  = pref + warpoff;
    unsigned total = aux[2 + 31];             // 8192
    unsigned suf   = total - (incl - s4);     // S[4t] = #keys in buckets >= 4t
    unsigned off0 = suf - h0;                 // off[v] = S[v+1]
    unsigned off1 = off0 - h1;
    unsigned off2 = off1 - h2;
    unsigned off3 = off2 - h3;
    unsigned best = 4 * t;
    if (off0 >= KOUT) best = 4 * t + 1;
    if (off1 >= KOUT) best = 4 * t + 2;
    if (off2 >= KOUT) best = 4 * t + 3;
    if (suf >= KOUT) atomicMax(&aux[34], best);
    cur[4 * t] = off0; cur[4 * t + 1] = off1; cur[4 * t + 2] = off2; cur[4 * t + 3] = off3;
    __syncthreads();
    unsigned bstar = aux[34];

    // scatter candidates (bucket >= bstar) grouped by descending bucket
    #pragma unroll
    for (int r = 0; r < 8; ++r) {
        unsigned bk = bucket_of(k8[r]);
        if (bk >= bstar) {
            unsigned pos = atomicAdd(&cur[bk], 1u);
            if (pos < 2048) cand[pos] = k8[r];
        }
    }
    __syncthreads();

    // per-bucket insertion sort (descending by full 64-bit key -> exact
    // lax.top_k order: score desc, idx asc via ~idx low bits)
    {
        unsigned offs[4] = {off0, off1, off2, off3};
        #pragma unroll
        for (int v4 = 0; v4 < 4; ++v4) {
            unsigned v = 4 * t + v4;
            unsigned start = offs[v4];
            if (v >= bstar && start < KOUT) {
                unsigned end = min(cur[v], 2048u);
                for (unsigned a = start + 1; a < end; ++a) {
                    ull kvv = cand[a];
                    unsigned pos2 = a;
                    while (pos2 > start && cand[pos2 - 1] < kvv) { cand[pos2] = cand[pos2 - 1]; --pos2; }
                    cand[pos2] = kvv;
                }
            }
        }
    }
    __syncthreads();

    // ---- epilogue: rank t; lafs_out [4,1024,2,3] ++ scores_out [4,1024] ----
    {
        ull fk = cand[t];
        int idx = (int)((~(unsigned)fk) & (NPTS - 1));
        unsigned mm = (unsigned)(fk >> 32);
        unsigned sbb = (mm & 0x80000000u) ? (mm & 0x7FFFFFFFu) : ~mm;
        float sc = __uint_as_float(sbb);

        const float2* srcL = reinterpret_cast<const float2*>(lafs + (size_t)(base + idx) * 6);
        float2*       dst  = reinterpret_cast<float2*>(out + (size_t)(batch * KOUT + t) * 6);
        dst[0] = srcL[0];
        dst[1] = srcL[1];
        dst[2] = srcL[2];
        out[BATCH * KOUT * 6 + batch * KOUT + t] = sc;
    }
}

extern "C" void kernel_launch(void* const* d_in, const int* in_sizes, int n_in,
                              void* d_out, int out_size) {
    const float* lafs   = (const float*)d_in[0];
    const float* scores = (const float*)d_in[1];
    float* out = (float*)d_out;

    fused_kernel<<<32, 1024>>>(lafs, scores, out);
}